// round 5
// baseline (speedup 1.0000x reference)
#include <cuda_runtime.h>
#include <math.h>

#define E 1024
#define H 4096

// Scratch (allocation-free per harness rules)
__device__ __align__(16) float g_xi[H];
__device__ int g_hflag;

__device__ __forceinline__ float sigmoidf(float x) {
    return 1.0f / (1.0f + expf(-x));
}

// ---------------------------------------------------------------------------
// K0: g_hflag = any(h0 != 0). Recomputed fresh every call (deterministic).
// ---------------------------------------------------------------------------
__global__ void k_hflag(const float* __restrict__ h0) {
    int any = 0;
    for (int i = threadIdx.x; i < H; i += blockDim.x)
        any |= (h0[i] != 0.0f);
    int r = __syncthreads_or(any);
    if (threadIdx.x == 0) g_hflag = (r != 0);
}

// ---------------------------------------------------------------------------
// K1: xi[row] = dot(W_in[row, :], x) + b_in[row].  One block per row.
// E = 1024 -> 256 float4 per row -> exactly one float4 per thread.
// ---------------------------------------------------------------------------
__global__ void k_xi(const float* __restrict__ x,
                     const float* __restrict__ W_in,
                     const float* __restrict__ b_in) {
    const int row = blockIdx.x;
    const int t = threadIdx.x;  // 256 threads
    const float4* __restrict__ w = (const float4*)(W_in + (size_t)row * E);
    const float4* __restrict__ xv = (const float4*)x;

    float4 a = w[t];
    float4 b = xv[t];
    float acc = a.x * b.x + a.y * b.y + a.z * b.z + a.w * b.w;

    #pragma unroll
    for (int o = 16; o; o >>= 1) acc += __shfl_down_sync(0xFFFFFFFFu, acc, o);

    __shared__ float sred[8];
    if ((t & 31) == 0) sred[t >> 5] = acc;
    __syncthreads();
    if (t < 8) {
        float v = sred[t];
        #pragma unroll
        for (int o = 4; o; o >>= 1) v += __shfl_down_sync(0xFFu, v, o);
        if (t == 0) g_xi[row] = v + b_in[row];
    }
}

// ---------------------------------------------------------------------------
// K2: for element j, compute 4 gate dot-products (rows j, H+j, 2H+j, 3H+j of
// W_ih against xi, plus optional W_hh against h0), fuse LSTM activations,
// write h1 -> d_out[1024+j], c1 -> d_out[1024+H+j].
// ---------------------------------------------------------------------------
__global__ void k_gates(const float* __restrict__ W_ih,
                        const float* __restrict__ W_hh,
                        const float* __restrict__ b_ih,
                        const float* __restrict__ b_hh,
                        const float* __restrict__ h0,
                        const float* __restrict__ c0,
                        float* __restrict__ out) {
    const int j = blockIdx.x;
    const int t = threadIdx.x;  // 256 threads

    __shared__ __align__(16) float sxi[H];  // 16 KB
    float4* s4 = (float4*)sxi;
    const float4* xi4 = (const float4*)g_xi;
    #pragma unroll
    for (int i = 0; i < 4; i++) s4[t + i * 256] = xi4[t + i * 256];
    __syncthreads();

    float acc[4] = {0.f, 0.f, 0.f, 0.f};

    #pragma unroll
    for (int g = 0; g < 4; g++) {
        const float4* __restrict__ w =
            (const float4*)(W_ih + ((size_t)g * H + j) * (size_t)H);
        #pragma unroll
        for (int i = 0; i < 4; i++) {
            float4 a = w[t + i * 256];
            float4 b = s4[t + i * 256];
            acc[g] += a.x * b.x + a.y * b.y + a.z * b.z + a.w * b.w;
        }
    }

    if (g_hflag) {  // uniform branch: skipped entirely when h0 == 0
        const float4* __restrict__ hv = (const float4*)h0;
        #pragma unroll
        for (int g = 0; g < 4; g++) {
            const float4* __restrict__ w =
                (const float4*)(W_hh + ((size_t)g * H + j) * (size_t)H);
            #pragma unroll
            for (int i = 0; i < 4; i++) {
                float4 a = w[t + i * 256];
                float4 b = hv[t + i * 256];
                acc[g] += a.x * b.x + a.y * b.y + a.z * b.z + a.w * b.w;
            }
        }
    }

    // Reduce 4 accumulators: warp shuffle, then cross-warp via shared.
    #pragma unroll
    for (int o = 16; o; o >>= 1) {
        #pragma unroll
        for (int g = 0; g < 4; g++)
            acc[g] += __shfl_down_sync(0xFFFFFFFFu, acc[g], o);
    }

    __shared__ float sred[8][4];
    if ((t & 31) == 0) {
        #pragma unroll
        for (int g = 0; g < 4; g++) sred[t >> 5][g] = acc[g];
    }
    __syncthreads();

    if (t == 0) {
        float v[4];
        #pragma unroll
        for (int g = 0; g < 4; g++) {
            float s = 0.f;
            #pragma unroll
            for (int w = 0; w < 8; w++) s += sred[w][g];
            v[g] = s + b_ih[g * H + j] + b_hh[g * H + j];
        }
        float i_s = sigmoidf(v[0]);
        float f_s = sigmoidf(v[1]);
        float g_t = tanhf(v[2]);
        float o_s = sigmoidf(v[3]);
        float c1 = f_s * c0[j] + i_s * g_t;
        float h1 = o_s * tanhf(c1);
        out[E + j] = h1;          // h1 region
        out[E + H + j] = c1;      // c1 region
    }
}

// ---------------------------------------------------------------------------
// K3: out[row] = dot(W_out[row, :], h1) + b_out[row]. h1 read from d_out+E.
// H = 4096 -> 1024 float4 per row -> 4 float4 per thread (256 threads).
// ---------------------------------------------------------------------------
__global__ void k_out(const float* __restrict__ W_out,
                      const float* __restrict__ b_out,
                      const float* __restrict__ h1,
                      float* __restrict__ out) {
    const int row = blockIdx.x;
    const int t = threadIdx.x;  // 256 threads
    const float4* __restrict__ w = (const float4*)(W_out + (size_t)row * H);
    const float4* __restrict__ hv = (const float4*)h1;

    float acc = 0.f;
    #pragma unroll
    for (int i = 0; i < 4; i++) {
        float4 a = w[t + i * 256];
        float4 b = hv[t + i * 256];
        acc += a.x * b.x + a.y * b.y + a.z * b.z + a.w * b.w;
    }

    #pragma unroll
    for (int o = 16; o; o >>= 1) acc += __shfl_down_sync(0xFFFFFFFFu, acc, o);

    __shared__ float sred[8];
    if ((t & 31) == 0) sred[t >> 5] = acc;
    __syncthreads();
    if (t < 8) {
        float v = sred[t];
        #pragma unroll
        for (int o = 4; o; o >>= 1) v += __shfl_down_sync(0xFFu, v, o);
        if (t == 0) out[row] = v + b_out[row];
    }
}

// ---------------------------------------------------------------------------
// Inputs (metadata order): 0:x 1:h0 2:c0 3:W_in 4:b_in 5:W_ih 6:W_hh
//                          7:b_ih 8:b_hh 9:W_out 10:b_out
// Output layout: [out (1024), h1 (4096), c1 (4096)]
// ---------------------------------------------------------------------------
extern "C" void kernel_launch(void* const* d_in, const int* in_sizes, int n_in,
                              void* d_out, int out_size) {
    const float* x     = (const float*)d_in[0];
    const float* h0    = (const float*)d_in[1];
    const float* c0    = (const float*)d_in[2];
    const float* W_in  = (const float*)d_in[3];
    const float* b_in  = (const float*)d_in[4];
    const float* W_ih  = (const float*)d_in[5];
    const float* W_hh  = (const float*)d_in[6];
    const float* b_ih  = (const float*)d_in[7];
    const float* b_hh  = (const float*)d_in[8];
    const float* W_out = (const float*)d_in[9];
    const float* b_out = (const float*)d_in[10];
    float* out = (float*)d_out;

    k_hflag<<<1, 256>>>(h0);
    k_xi<<<H, 256>>>(x, W_in, b_in);
    k_gates<<<H, 256>>>(W_ih, W_hh, b_ih, b_hh, h0, c0, out);
    k_out<<<E, 256>>>(W_out, b_out, out + E, out);
}

// round 6
// speedup vs baseline: 1.0052x; 1.0052x over previous
#include <cuda_runtime.h>
#include <math.h>

#define E 1024
#define H 4096

// Scratch (allocation-free per harness rules)
__device__ __align__(16) float g_xi[H];
__device__ int g_hflag;

__device__ __forceinline__ float sigmoidf(float x) {
    return 1.0f / (1.0f + expf(-x));
}

// ---------------------------------------------------------------------------
// K1: xi[row] = dot(W_in[row,:], x) + b_in[row].
// Warp-per-row, 8 rows per block (256 threads). grid = 512 + 1; the extra
// block computes g_hflag = any(h0 != 0).
// ---------------------------------------------------------------------------
__global__ __launch_bounds__(256) void k_xi(const float* __restrict__ x,
                                            const float* __restrict__ W_in,
                                            const float* __restrict__ b_in,
                                            const float* __restrict__ h0) {
    const int t = threadIdx.x;

    if (blockIdx.x == gridDim.x - 1) {
        // hflag block: h0 has 4096 floats = 1024 float4; 4 per thread.
        const float4* h4 = (const float4*)h0;
        int any = 0;
        #pragma unroll
        for (int i = 0; i < 4; i++) {
            float4 v = h4[t + i * 256];
            any |= (v.x != 0.f) | (v.y != 0.f) | (v.z != 0.f) | (v.w != 0.f);
        }
        int r = __syncthreads_or(any);
        if (t == 0) g_hflag = (r != 0);
        return;
    }

    __shared__ __align__(16) float sx[E];  // 4 KB
    float4* sx4 = (float4*)sx;
    sx4[t] = ((const float4*)x)[t];       // 256 float4 = 1024 floats
    __syncthreads();

    const int w = t >> 5, lane = t & 31;
    const int row = blockIdx.x * 8 + w;
    const float4* __restrict__ wr = (const float4*)(W_in + (size_t)row * E);

    float acc = 0.f;
    #pragma unroll
    for (int i = 0; i < 8; i++) {
        float4 a = wr[lane + 32 * i];
        float4 b = sx4[lane + 32 * i];
        acc += a.x * b.x + a.y * b.y + a.z * b.z + a.w * b.w;
    }
    #pragma unroll
    for (int o = 16; o; o >>= 1) acc += __shfl_down_sync(0xFFFFFFFFu, acc, o);
    if (lane == 0) g_xi[row] = acc + b_in[row];
}

// ---------------------------------------------------------------------------
// K2: gate kernel. Block handles 8 j's (one per warp); warp computes all 4
// gate dot products for its j (rows j, H+j, 2H+j, 3H+j of W_ih vs xi, plus
// optional W_hh vs h0), fuses LSTM activations, writes h1/c1 into d_out.
// xi (and h0 when needed) staged in smem once per block.
// ---------------------------------------------------------------------------
__global__ __launch_bounds__(256) void k_gates(const float* __restrict__ W_ih,
                                               const float* __restrict__ W_hh,
                                               const float* __restrict__ b_ih,
                                               const float* __restrict__ b_hh,
                                               const float* __restrict__ h0,
                                               const float* __restrict__ c0,
                                               float* __restrict__ out) {
    const int t = threadIdx.x;
    const int w = t >> 5, lane = t & 31;
    const int j = blockIdx.x * 8 + w;
    const int hflag = g_hflag;  // uniform

    __shared__ __align__(16) float sxi[H];  // 16 KB
    __shared__ __align__(16) float shv[H];  // 16 KB (used only if hflag)
    float4* sxi4 = (float4*)sxi;
    const float4* gxi4 = (const float4*)g_xi;
    #pragma unroll
    for (int i = 0; i < 4; i++) sxi4[t + i * 256] = gxi4[t + i * 256];
    if (hflag) {
        float4* sh4 = (float4*)shv;
        const float4* h4 = (const float4*)h0;
        #pragma unroll
        for (int i = 0; i < 4; i++) sh4[t + i * 256] = h4[t + i * 256];
    }
    __syncthreads();

    const size_t rstride = (size_t)H * H;  // gate-to-gate row offset in elems
    const float4* __restrict__ w0 = (const float4*)(W_ih + (size_t)j * H);
    const float4* __restrict__ w1 = (const float4*)(W_ih + (size_t)j * H + rstride);
    const float4* __restrict__ w2 = (const float4*)(W_ih + (size_t)j * H + 2 * rstride);
    const float4* __restrict__ w3 = (const float4*)(W_ih + (size_t)j * H + 3 * rstride);

    float a0 = 0.f, a1 = 0.f, a2 = 0.f, a3 = 0.f;
    #pragma unroll 4
    for (int i = 0; i < 32; i++) {
        const int k = lane + 32 * i;
        float4 xv = sxi4[k];
        float4 r0 = w0[k], r1 = w1[k], r2 = w2[k], r3 = w3[k];
        a0 += r0.x * xv.x + r0.y * xv.y + r0.z * xv.z + r0.w * xv.w;
        a1 += r1.x * xv.x + r1.y * xv.y + r1.z * xv.z + r1.w * xv.w;
        a2 += r2.x * xv.x + r2.y * xv.y + r2.z * xv.z + r2.w * xv.w;
        a3 += r3.x * xv.x + r3.y * xv.y + r3.z * xv.z + r3.w * xv.w;
    }

    if (hflag) {  // uniform branch: skipped entirely when h0 == 0
        const float4* sh4 = (const float4*)shv;
        const float4* __restrict__ v0 = (const float4*)(W_hh + (size_t)j * H);
        const float4* __restrict__ v1 = (const float4*)(W_hh + (size_t)j * H + rstride);
        const float4* __restrict__ v2 = (const float4*)(W_hh + (size_t)j * H + 2 * rstride);
        const float4* __restrict__ v3 = (const float4*)(W_hh + (size_t)j * H + 3 * rstride);
        #pragma unroll 4
        for (int i = 0; i < 32; i++) {
            const int k = lane + 32 * i;
            float4 hv = sh4[k];
            float4 r0 = v0[k], r1 = v1[k], r2 = v2[k], r3 = v3[k];
            a0 += r0.x * hv.x + r0.y * hv.y + r0.z * hv.z + r0.w * hv.w;
            a1 += r1.x * hv.x + r1.y * hv.y + r1.z * hv.z + r1.w * hv.w;
            a2 += r2.x * hv.x + r2.y * hv.y + r2.z * hv.z + r2.w * hv.w;
            a3 += r3.x * hv.x + r3.y * hv.y + r3.z * hv.z + r3.w * hv.w;
        }
    }

    #pragma unroll
    for (int o = 16; o; o >>= 1) {
        a0 += __shfl_down_sync(0xFFFFFFFFu, a0, o);
        a1 += __shfl_down_sync(0xFFFFFFFFu, a1, o);
        a2 += __shfl_down_sync(0xFFFFFFFFu, a2, o);
        a3 += __shfl_down_sync(0xFFFFFFFFu, a3, o);
    }

    if (lane == 0) {
        float vi = a0 + b_ih[j]         + b_hh[j];
        float vf = a1 + b_ih[H + j]     + b_hh[H + j];
        float vg = a2 + b_ih[2 * H + j] + b_hh[2 * H + j];
        float vo = a3 + b_ih[3 * H + j] + b_hh[3 * H + j];
        float c1 = sigmoidf(vf) * c0[j] + sigmoidf(vi) * tanhf(vg);
        float h1 = sigmoidf(vo) * tanhf(c1);
        out[E + j] = h1;        // h1 region
        out[E + H + j] = c1;    // c1 region
    }
}

// ---------------------------------------------------------------------------
// K3: out[row] = dot(W_out[row,:], h1) + b_out[row].
// Warp-per-row, 8 rows per block. grid = 128. h1 staged in smem.
// ---------------------------------------------------------------------------
__global__ __launch_bounds__(256) void k_out(const float* __restrict__ W_out,
                                             const float* __restrict__ b_out,
                                             const float* __restrict__ h1,
                                             float* __restrict__ out) {
    const int t = threadIdx.x;

    __shared__ __align__(16) float sh[H];  // 16 KB
    float4* sh4 = (float4*)sh;
    const float4* h4 = (const float4*)h1;
    #pragma unroll
    for (int i = 0; i < 4; i++) sh4[t + i * 256] = h4[t + i * 256];
    __syncthreads();

    const int w = t >> 5, lane = t & 31;
    const int row = blockIdx.x * 8 + w;
    const float4* __restrict__ wr = (const float4*)(W_out + (size_t)row * H);

    float acc = 0.f;
    #pragma unroll 8
    for (int i = 0; i < 32; i++) {
        float4 a = wr[lane + 32 * i];
        float4 b = sh4[lane + 32 * i];
        acc += a.x * b.x + a.y * b.y + a.z * b.z + a.w * b.w;
    }
    #pragma unroll
    for (int o = 16; o; o >>= 1) acc += __shfl_down_sync(0xFFFFFFFFu, acc, o);
    if (lane == 0) out[row] = acc + b_out[row];
}

// ---------------------------------------------------------------------------
// Inputs (metadata order): 0:x 1:h0 2:c0 3:W_in 4:b_in 5:W_ih 6:W_hh
//                          7:b_ih 8:b_hh 9:W_out 10:b_out
// Output layout: [out (1024), h1 (4096), c1 (4096)]
// ---------------------------------------------------------------------------
extern "C" void kernel_launch(void* const* d_in, const int* in_sizes, int n_in,
                              void* d_out, int out_size) {
    const float* x     = (const float*)d_in[0];
    const float* h0    = (const float*)d_in[1];
    const float* c0    = (const float*)d_in[2];
    const float* W_in  = (const float*)d_in[3];
    const float* b_in  = (const float*)d_in[4];
    const float* W_ih  = (const float*)d_in[5];
    const float* W_hh  = (const float*)d_in[6];
    const float* b_ih  = (const float*)d_in[7];
    const float* b_hh  = (const float*)d_in[8];
    const float* W_out = (const float*)d_in[9];
    const float* b_out = (const float*)d_in[10];
    float* out = (float*)d_out;

    k_xi<<<H / 8 + 1, 256>>>(x, W_in, b_in, h0);           // rows + hflag block
    k_gates<<<H / 8, 256>>>(W_ih, W_hh, b_ih, b_hh, h0, c0, out);
    k_out<<<E / 8, 256>>>(W_out, b_out, out + E, out);
}